// round 2
// baseline (speedup 1.0000x reference)
#include <cuda_runtime.h>

// Problem constants (fixed shapes from reference setup_inputs)
#define DD 160
#define HH 192
#define WW 160
static constexpr int VOL = DD * HH * WW;   // 4,915,200

__global__ void __launch_bounds__(256)
st_warp_kernel(const float* __restrict__ src,
               const float* __restrict__ flow1,
               const float* __restrict__ flow2,
               const float* __restrict__ rf_p,
               float* __restrict__ out)
{
    const int i = blockIdx.x * blockDim.x + threadIdx.x;
    if (i >= VOL) return;

    const float rf = __ldg(rf_p);

    const int w = i % WW;
    const int h = (i / WW) % HH;
    const int d = i / (WW * HH);

    // flow2 channels (channel order: d, h, w)
    const float f2d = flow2[i];
    const float f2h = flow2[i + VOL];
    const float f2w = flow2[i + 2 * VOL];

    // ---- Stage 1: warp flow1 at grid2 = grid + rf*flow2 (UNNORMALIZED coords
    // fed into a normalized-coordinate sampler -> almost always out of bounds)
    const float gd = (float)d + f2d * rf;
    const float gh = (float)h + f2h * rf;
    const float gw = (float)w + f2w * rf;

    // sample-grid reversal: (x,y,z) = (gw, gh, gd); unnorm align_corners=False
    const float ix = ((gw + 1.0f) * (float)WW - 1.0f) * 0.5f;
    const float iy = ((gh + 1.0f) * (float)HH - 1.0f) * 0.5f;
    const float iz = ((gd + 1.0f) * (float)DD - 1.0f) * 0.5f;

    float w1d = 0.0f, w1h = 0.0f, w1w = 0.0f;
    if (ix > -1.0f && ix < (float)WW &&
        iy > -1.0f && iy < (float)HH &&
        iz > -1.0f && iz < (float)DD) {
        const float x0f = floorf(ix), y0f = floorf(iy), z0f = floorf(iz);
        const float tx = ix - x0f, ty = iy - y0f, tz = iz - z0f;
        const int x0 = (int)x0f, y0 = (int)y0f, z0 = (int)z0f;
        #pragma unroll
        for (int dz = 0; dz < 2; dz++) {
            #pragma unroll
            for (int dy = 0; dy < 2; dy++) {
                #pragma unroll
                for (int dx = 0; dx < 2; dx++) {
                    const int zc = z0 + dz, yc = y0 + dy, xc = x0 + dx;
                    if ((unsigned)zc < (unsigned)DD &&
                        (unsigned)yc < (unsigned)HH &&
                        (unsigned)xc < (unsigned)WW) {
                        const float wt = (dz ? tz : 1.0f - tz) *
                                         (dy ? ty : 1.0f - ty) *
                                         (dx ? tx : 1.0f - tx);
                        const int off = (zc * HH + yc) * WW + xc;
                        w1d += wt * __ldg(flow1 + off);
                        w1h += wt * __ldg(flow1 + off + VOL);
                        w1w += wt * __ldg(flow1 + off + 2 * VOL);
                    }
                }
            }
        }
    }

    // ---- out_flow = flow1_warped + flow2  (output #2)
    const float ofd = w1d + f2d;
    const float ofh = w1h + f2h;
    const float ofw = w1w + f2w;
    out[VOL + i]           = ofd;
    out[VOL + i + VOL]     = ofh;
    out[VOL + i + 2 * VOL] = ofw;

    // ---- Stage 2: properly normalized sample of src at grid + rf*out_flow
    const float nd = (float)d + ofd * rf;
    const float nh = (float)h + ofh * rf;
    const float nw = (float)w + ofw * rf;
    // normalize: 2*(loc/(S-1) - 0.5), then unnorm align_corners=False
    const float nld = 2.0f * (nd / (float)(DD - 1) - 0.5f);
    const float nlh = 2.0f * (nh / (float)(HH - 1) - 0.5f);
    const float nlw = 2.0f * (nw / (float)(WW - 1) - 0.5f);
    const float jx = ((nlw + 1.0f) * (float)WW - 1.0f) * 0.5f;
    const float jy = ((nlh + 1.0f) * (float)HH - 1.0f) * 0.5f;
    const float jz = ((nld + 1.0f) * (float)DD - 1.0f) * 0.5f;

    float val = 0.0f;
    if (jx > -1.0f && jx < (float)WW &&
        jy > -1.0f && jy < (float)HH &&
        jz > -1.0f && jz < (float)DD) {
        const float x0f = floorf(jx), y0f = floorf(jy), z0f = floorf(jz);
        const float tx = jx - x0f, ty = jy - y0f, tz = jz - z0f;
        const int x0 = (int)x0f, y0 = (int)y0f, z0 = (int)z0f;
        #pragma unroll
        for (int dz = 0; dz < 2; dz++) {
            #pragma unroll
            for (int dy = 0; dy < 2; dy++) {
                #pragma unroll
                for (int dx = 0; dx < 2; dx++) {
                    const int zc = z0 + dz, yc = y0 + dy, xc = x0 + dx;
                    if ((unsigned)zc < (unsigned)DD &&
                        (unsigned)yc < (unsigned)HH &&
                        (unsigned)xc < (unsigned)WW) {
                        const float wt = (dz ? tz : 1.0f - tz) *
                                         (dy ? ty : 1.0f - ty) *
                                         (dx ? tx : 1.0f - tx);
                        val += wt * __ldg(src + (zc * HH + yc) * WW + xc);
                    }
                }
            }
        }
    }
    out[i] = val;
}

extern "C" void kernel_launch(void* const* d_in, const int* in_sizes, int n_in,
                              void* d_out, int out_size)
{
    const float* src   = (const float*)d_in[0];
    const float* flow1 = (const float*)d_in[1];
    const float* flow2 = (const float*)d_in[2];
    // d_in[3] is the meshgrid 'grid' input — recomputed analytically in-kernel.
    const float* rf    = (const float*)d_in[4];
    float* out = (float*)d_out;

    const int threads = 256;
    const int blocks = (VOL + threads - 1) / threads;
    st_warp_kernel<<<blocks, threads>>>(src, flow1, flow2, rf, out);
}